// round 10
// baseline (speedup 1.0000x reference)
#include <cuda_runtime.h>

#define NA   3
#define NC   20
#define NCH  25      // 5 + NC
#define NT   256     // number of targets
#define EPSF 1e-7f

// Accumulators. Zero-initialized at module load; the finalizing block
// re-zeroes them so every graph replay starts clean.
__device__ double   g_obj[3];
__device__ float    g_corr[3];
__device__ float    g_box;
__device__ float    g_cls;
__device__ unsigned g_done;

__device__ __forceinline__ float sigmoidf(float x) {
    return 1.f / (1.f + __expf(-x));
}
// factor (1 + e^x); product of a group, then one log = softplus group-sum
__device__ __forceinline__ float spf(float x) {
    return 1.f + __expf(x);
}

__device__ __forceinline__ float warpReduceSum(float v) {
    #pragma unroll
    for (int o = 16; o > 0; o >>= 1)
        v += __shfl_xor_sync(0xffffffffu, v, o);
    return v;
}

// Homogeneous grid: 144 blocks. Each block does 16 target units (block-uniform
// scale s = bid/48 and anchor a = (bid/16)%3) plus an exact 1400-float4 slice
// of the objectness softplus sweep (144 * 1400 = 201600 float4 total).
__global__ void __launch_bounds__(256) fused_kernel(
    const float* __restrict__ p0,
    const float* __restrict__ p1,
    const float* __restrict__ p2,
    const float* __restrict__ tg,
    float* __restrict__ out, int out_size)
{
    const int bid = blockIdx.x;
    const int t   = threadIdx.x;
    const int lid = t & 31;

    __shared__ float s_t[NT * 6];
    __shared__ int   s_key[NT];

    for (int i = t; i < NT * 6; i += 256) s_t[i] = tg[i];
    __syncthreads();

    // block-uniform target geometry
    const int s  = bid / 48;                 // scale 0..2
    const int a  = (bid / 16) % 3;           // anchor
    const int H  = (s == 0) ? 80 : (s == 1) ? 40 : 20;
    const int W  = H;
    const int HW = H * W;
    const float* p = (s == 0) ? p0 : (s == 1) ? p1 : p2;
    const float fw = (float)W, fh = (float)H;

    // every thread computes the dedup key for target t at this block's scale
    {
        const int   kb = (int)s_t[t * 6 + 0];
        const float kx = s_t[t * 6 + 2];
        const float ky = s_t[t * 6 + 3];
        const int kgi = (int)fminf(fmaxf(kx * fw, 0.f), fw - 1.f);
        const int kgj = (int)fminf(fmaxf(ky * fh, 0.f), fh - 1.f);
        s_key[t] = (kb << 14) | (kgj << 7) | kgi;
    }
    __syncthreads();

    // ================= target part: threads 0..15 =================
    float lbox = 0.f, csum = 0.f, corr = 0.f;
    if (t < 16) {
        const int n = (bid & 15) * 16 + t;   // this thread's target
        const int   bi = (int)s_t[n * 6 + 0];
        const int   ci = (int)s_t[n * 6 + 1];
        const float cx = s_t[n * 6 + 2];
        const float cy = s_t[n * 6 + 3];
        const float tw = s_t[n * 6 + 4];
        const float th = s_t[n * 6 + 5];

        const int gi = (int)fminf(fmaxf(cx * fw, 0.f), fw - 1.f);
        const int gj = (int)fminf(fmaxf(cy * fh, 0.f), fh - 1.f);
        const int key = (bi << 14) | (gj << 7) | gi;

        const float* cellp = p + ((size_t)(bi * NA * NCH + a * NCH)) * HW
                               + (size_t)gj * W + gi;

        // issue ALL scattered loads up front (high MLP)
        const float x0 = cellp[0];
        const float x1 = cellp[HW];
        float xv[NC];
        #pragma unroll
        for (int c = 0; c < NC; c++) xv[c] = cellp[(size_t)(5 + c) * HW];
        const float xci = cellp[(size_t)(5 + ci) * HW];
        float c0 = 0.f, c1 = 0.f, c2v = 0.f;
        const float* op = p + ((size_t)(bi * NA * NCH)) * HW + (size_t)gj * W + gi;
        if (a == 0) {
            c0  = op[(size_t)4 * HW];
            c1  = op[(size_t)(NCH + 4) * HW];
            c2v = op[(size_t)(2 * NCH + 4) * HW];
        }

        const float sx = sigmoidf(x0);
        const float sy = sigmoidf(x1);

        const float twh = tw * fw * 0.5f;
        const float thh = th * fh * 0.5f;
        const float gif = (float)gi, gjf = (float)gj;

        const float px1 = (sx + gif - twh) / fw;
        const float py1 = (sy + gjf - thh) / fh;
        const float px2 = (sx + gif + twh) / fw;
        const float py2 = (sy + gjf + thh) / fh;

        const float tx1 = cx - tw * 0.5f;
        const float ty1 = cy - th * 0.5f;
        const float tx2 = cx + tw * 0.5f;
        const float ty2 = cy + th * 0.5f;

        // CIoU loss
        const float ix1 = fmaxf(px1, tx1), iy1 = fmaxf(py1, ty1);
        const float ix2 = fminf(px2, tx2), iy2 = fminf(py2, ty2);
        const float inter  = fmaxf(ix2 - ix1, 0.f) * fmaxf(iy2 - iy1, 0.f);
        const float area_p = (px2 - px1) * (py2 - py1);
        const float area_t = (tx2 - tx1) * (ty2 - ty1);
        const float uni = area_p + area_t - inter + EPSF;
        const float iou = inter / uni;
        const float ex1 = fminf(px1, tx1), ey1 = fminf(py1, ty1);
        const float ex2 = fmaxf(px2, tx2), ey2 = fmaxf(py2, ty2);
        const float c2  = (ex2 - ex1) * (ex2 - ex1) + (ey2 - ey1) * (ey2 - ey1) + EPSF;
        const float dxc = (px1 + px2) * 0.5f - (tx1 + tx2) * 0.5f;
        const float dyc = (py1 + py2) * 0.5f - (ty1 + ty2) * 0.5f;
        const float rho2 = dxc * dxc + dyc * dyc;
        const float pw  = fmaxf(px2 - px1, EPSF);
        const float ph  = fmaxf(py2 - py1, EPSF);
        const float twc = fmaxf(tx2 - tx1, EPSF);
        const float thc = fmaxf(ty2 - ty1, EPSF);
        const float dd  = atanf(twc / thc) - atanf(pw / ph);
        const float v   = 0.4052847345693511f * dd * dd;   // 4/pi^2
        const float alpha = v / (1.f - iou + v + EPSF);
        lbox = 1.f - (iou - rho2 / c2 - alpha * v);

        // cls BCE: [log prod(1+e^x) - x_ci] / NC  (4-way ILP product)
        float pr0 = 1.f, pr1 = 1.f, pr2 = 1.f, pr3 = 1.f;
        #pragma unroll
        for (int c = 0; c < NC; c += 4) {
            pr0 *= spf(xv[c]);
            pr1 *= spf(xv[c + 1]);
            pr2 *= spf(xv[c + 2]);
            pr3 *= spf(xv[c + 3]);
        }
        csum = (__logf((pr0 * pr1) * (pr2 * pr3)) - xci) * (1.f / (float)NC);

        // obj correction for first occurrence of this cell (a==0 lanes only)
        if (a == 0) {
            bool dup = false;
            #pragma unroll 4
            for (int m = 0; m < n; m++)
                dup |= (s_key[m] == key);
            corr = dup ? 0.f : -(c0 + c1 + c2v);
        }
    }

    // ================= sweep part: all threads, 1400 float4 / block =================
    // f4 ranges: s0 [0,153600), s1 [153600,192000), s2 [192000,201600)
    float4 vv[6];
    int    vsc[6];
    bool   vok[6];
    const int cbase = bid * 1400;
    #pragma unroll
    for (int i = 0; i < 6; i++) {
        const int off = t + 256 * i;
        vok[i] = (off < 1400);
        vsc[i] = 0;
        if (vok[i]) {
            const int pos = cbase + off;
            const float4* q;
            if (pos < 153600) {
                const int plane = pos / 1600;
                q = (const float4*)p0 + pos + 1600 * (24 * plane + 4);
                vsc[i] = 0;
            } else if (pos < 192000) {
                const int r = pos - 153600;
                const int plane = r / 400;
                q = (const float4*)p1 + r + 400 * (24 * plane + 4);
                vsc[i] = 1;
            } else {
                const int r = pos - 192000;
                const int plane = r / 100;
                q = (const float4*)p2 + r + 100 * (24 * plane + 4);
                vsc[i] = 2;
            }
            vv[i] = *q;   // 6 independent loads, hoisted: MLP ~6
        }
    }
    float o0 = 0.f, o1 = 0.f, o2 = 0.f;
    #pragma unroll
    for (int i = 0; i < 6; i++) {
        if (vok[i]) {
            const float4 v4 = vv[i];
            const float f = (spf(v4.x) * spf(v4.y)) * (spf(v4.z) * spf(v4.w));
            const float l = __logf(f);            // product of 4 <= ~2.6e10, safe
            if      (vsc[i] == 0) o0 += l;
            else if (vsc[i] == 1) o1 += l;
            else                  o2 += l;
        }
    }

    // ================= reductions =================
    float rb = warpReduceSum(lbox);   // nonzero only in warp 0
    float rc = warpReduceSum(csum);
    float ro = warpReduceSum(corr);
    float r0 = warpReduceSum(o0);
    float r1 = warpReduceSum(o1);
    float r2 = warpReduceSum(o2);
    if (lid == 0) {
        if (rb != 0.f) atomicAdd(&g_box, rb);
        if (rc != 0.f) atomicAdd(&g_cls, rc);
        if (ro != 0.f) atomicAdd(&g_corr[s], ro);
        if (r0 != 0.f) atomicAdd(&g_obj[0], (double)r0);
        if (r1 != 0.f) atomicAdd(&g_obj[1], (double)r1);
        if (r2 != 0.f) atomicAdd(&g_obj[2], (double)r2);
        __threadfence();   // order my REDs before the barrier
    }
    __syncthreads();       // all warps' atomics fenced before finalize

    // ================= device-side finalize (last block) =================
    if (t == 0) {
        __threadfence();
        unsigned old = atomicAdd(&g_done, 1u);
        if (old == gridDim.x - 1) {
            const double cnt[3] = {614400.0, 153600.0, 38400.0};
            double lod = 0.0;
            for (int k = 0; k < 3; k++)
                lod += (g_obj[k] + (double)g_corr[k]) / cnt[k];
            const float lo = (float)lod;
            const float lb = g_box * (1.f / 2304.f);   // N*A*3
            const float lc = g_cls * (1.f / 2304.f);
            const float total = 0.05f * lb + 1.0f * lo + 0.5f * lc;
            float vals[5] = {total, lb, lo, lc, 0.f};
            for (int i = 0; i < out_size; i++)
                out[i] = (i < 5) ? vals[i] : 0.f;
            // reset for next graph replay
            g_box = 0.f;
            g_cls = 0.f;
            for (int k = 0; k < 3; k++) { g_corr[k] = 0.f; g_obj[k] = 0.0; }
            g_done = 0u;
        }
    }
}

extern "C" void kernel_launch(void* const* d_in, const int* in_sizes, int n_in,
                              void* d_out, int out_size) {
    const float* p0 = (const float*)d_in[0];
    const float* p1 = (const float*)d_in[1];
    const float* p2 = (const float*)d_in[2];
    const float* tg = (const float*)d_in[3];
    (void)in_sizes; (void)n_in;

    // 144 homogeneous blocks: one wave, balanced gather+sweep per block
    fused_kernel<<<144, 256>>>(p0, p1, p2, tg, (float*)d_out, out_size);
}

// round 11
// speedup vs baseline: 1.0646x; 1.0646x over previous
#include <cuda_runtime.h>

#define NA   3
#define NC   20
#define NCH  25      // 5 + NC
#define NT   256     // number of targets
#define TPB  64      // targets per target-block (NT/4)
#define EPSF 1e-7f

// Accumulators. Zero-initialized at module load; the finalizing block
// re-zeroes them so every graph replay starts clean.
__device__ double   g_obj[3];
__device__ float    g_corr[3];
__device__ float    g_box;
__device__ float    g_cls;
__device__ unsigned g_done;

__device__ __forceinline__ float sigmoidf(float x) {
    return 1.f / (1.f + __expf(-x));
}
// factor (1 + e^x) via MUFU
__device__ __forceinline__ float spf(float x) {
    return 1.f + __expf(x);
}
// factor (1 + e^x) via FMA-pipe exp2 bit trick (no MUFU).
// |rel err| ~1e-4, minimax (near-zero bias). Safe for x in [-20, 30].
__device__ __forceinline__ float spf_poly(float x) {
    x = fminf(fmaxf(x, -20.f), 30.f);
    const float y = x * 1.44269504088896f;     // log2(e)
    const float r = rintf(y);
    const float f = y - r;
    // 2^f on [-0.5, 0.5], cubic minimax
    float p = fmaf(f, 0.0558263f, 0.2401536f);
    p = fmaf(f, p, 0.6931531f);
    p = fmaf(f, p, 0.9999993f);
    const int e = (int)r;
    const float s = __int_as_float(__float_as_int(p) + (e << 23));
    return 1.f + s;
}

__device__ __forceinline__ float warpReduceSum(float v) {
    #pragma unroll
    for (int o = 16; o > 0; o >>= 1)
        v += __shfl_xor_sync(0xffffffffu, v, o);
    return v;
}

// product of 8 factors: 6 via MUFU exp, 2 via FMA-pipe poly exp (pipe balance)
__device__ __forceinline__ float prod8(float4 a, float4 b) {
    return ((spf(a.x) * spf(a.y)) * (spf(a.z) * spf_poly(a.w)))
         * ((spf(b.x) * spf(b.y)) * (spf(b.z) * spf_poly(b.w)));
}

// 32-element softplus group-sum; requires HW4 % 8 == 0 (no plane straddle)
template<int HW4>
__device__ __forceinline__ float sweep32(const float* __restrict__ p, int e32) {
    const int f4    = e32 * 8;
    const int plane = f4 / HW4;                 // constant divisor -> mul/shift
    const float4* q = (const float4*)p + f4 + (size_t)HW4 * (24 * plane + 4);
    float4 v0 = q[0], v1 = q[1], v2 = q[2], v3 = q[3];
    float4 v4 = q[4], v5 = q[5], v6 = q[6], v7 = q[7];   // MLP = 8
    float pa = prod8(v0, v1);    // each product of 8 factors <= ~1e21, safe
    float pb = prod8(v2, v3);
    float pc = prod8(v4, v5);
    float pd = prod8(v6, v7);
    return (__logf(pa) + __logf(pb)) + (__logf(pc) + __logf(pd));
}

// 16-element variant for scale 2 (HW4 = 100, multiple of 4 only)
template<int HW4>
__device__ __forceinline__ float sweep16(const float* __restrict__ p, int e16) {
    const int f4    = e16 * 4;
    const int plane = f4 / HW4;
    const float4* q = (const float4*)p + f4 + (size_t)HW4 * (24 * plane + 4);
    float4 v0 = q[0], v1 = q[1], v2 = q[2], v3 = q[3];
    return __logf(prod8(v0, v1)) + __logf(prod8(v2, v3));
}

__global__ void __launch_bounds__(256) fused_kernel(
    const float* __restrict__ p0,
    const float* __restrict__ p1,
    const float* __restrict__ p2,
    const float* __restrict__ tg,
    float* __restrict__ out, int out_size)
{
    const int bid = blockIdx.x;
    const int t   = threadIdx.x;
    const int lid = t & 31;

    if (bid < 36) {
        // ------- target blocks: (scale, anchor, quarter), 64 targets each -------
        __shared__ float s_t[NT * 6];
        __shared__ int   s_key[NT];
        for (int i = t; i < NT * 6; i += 256) s_t[i] = tg[i];
        __syncthreads();

        const int s = bid / 12;                 // scale
        const int a = (bid / 4) % 3;            // anchor
        const int q4 = bid & 3;                 // quarter
        const int H  = (s == 0) ? 80 : (s == 1) ? 40 : 20;
        const int W  = H;
        const int HW = H * W;
        const float* p = (s == 0) ? p0 : (s == 1) ? p1 : p2;
        const float fw = (float)W, fh = (float)H;

        // every thread computes the key for target t (full table for dedup scan)
        {
            const int   kb = (int)s_t[t * 6 + 0];
            const float kx = s_t[t * 6 + 2];
            const float ky = s_t[t * 6 + 3];
            const int kgi = (int)fminf(fmaxf(kx * fw, 0.f), fw - 1.f);
            const int kgj = (int)fminf(fmaxf(ky * fh, 0.f), fh - 1.f);
            s_key[t] = (kb << 14) | (kgj << 7) | kgi;
        }
        __syncthreads();

        float lbox = 0.f, csum = 0.f, corr = 0.f;
        if (t < TPB) {
            const int n = q4 * TPB + t;         // this thread's target
            const int   bi = (int)s_t[n * 6 + 0];
            const int   ci = (int)s_t[n * 6 + 1];
            const float cx = s_t[n * 6 + 2];
            const float cy = s_t[n * 6 + 3];
            const float tw = s_t[n * 6 + 4];
            const float th = s_t[n * 6 + 5];

            const int gi = (int)fminf(fmaxf(cx * fw, 0.f), fw - 1.f);
            const int gj = (int)fminf(fmaxf(cy * fh, 0.f), fh - 1.f);
            const int key = (bi << 14) | (gj << 7) | gi;

            const float* cellp = p + ((size_t)(bi * NA * NCH + a * NCH)) * HW
                                   + (size_t)gj * W + gi;

            // ---- issue ALL scattered loads up front (high MLP) ----
            const float x0 = cellp[0];
            const float x1 = cellp[HW];
            float xv[NC];
            #pragma unroll
            for (int c = 0; c < NC; c++) xv[c] = cellp[(size_t)(5 + c) * HW];
            const float xci = cellp[(size_t)(5 + ci) * HW];
            float c0 = 0.f, c1 = 0.f, c2v = 0.f;
            const float* op = p + ((size_t)(bi * NA * NCH)) * HW + (size_t)gj * W + gi;
            if (a == 0) {
                c0  = op[(size_t)4 * HW];
                c1  = op[(size_t)(NCH + 4) * HW];
                c2v = op[(size_t)(2 * NCH + 4) * HW];
            }

            const float sx = sigmoidf(x0);
            const float sy = sigmoidf(x1);

            const float twh = tw * fw * 0.5f;
            const float thh = th * fh * 0.5f;
            const float gif = (float)gi, gjf = (float)gj;

            const float px1 = (sx + gif - twh) / fw;
            const float py1 = (sy + gjf - thh) / fh;
            const float px2 = (sx + gif + twh) / fw;
            const float py2 = (sy + gjf + thh) / fh;

            const float tx1 = cx - tw * 0.5f;
            const float ty1 = cy - th * 0.5f;
            const float tx2 = cx + tw * 0.5f;
            const float ty2 = cy + th * 0.5f;

            // CIoU loss
            const float ix1 = fmaxf(px1, tx1), iy1 = fmaxf(py1, ty1);
            const float ix2 = fminf(px2, tx2), iy2 = fminf(py2, ty2);
            const float inter  = fmaxf(ix2 - ix1, 0.f) * fmaxf(iy2 - iy1, 0.f);
            const float area_p = (px2 - px1) * (py2 - py1);
            const float area_t = (tx2 - tx1) * (ty2 - ty1);
            const float uni = area_p + area_t - inter + EPSF;
            const float iou = inter / uni;
            const float ex1 = fminf(px1, tx1), ey1 = fminf(py1, ty1);
            const float ex2 = fmaxf(px2, tx2), ey2 = fmaxf(py2, ty2);
            const float c2  = (ex2 - ex1) * (ex2 - ex1) + (ey2 - ey1) * (ey2 - ey1) + EPSF;
            const float dxc = (px1 + px2) * 0.5f - (tx1 + tx2) * 0.5f;
            const float dyc = (py1 + py2) * 0.5f - (ty1 + ty2) * 0.5f;
            const float rho2 = dxc * dxc + dyc * dyc;
            const float pw  = fmaxf(px2 - px1, EPSF);
            const float ph  = fmaxf(py2 - py1, EPSF);
            const float twc = fmaxf(tx2 - tx1, EPSF);
            const float thc = fmaxf(ty2 - ty1, EPSF);
            const float dd  = atanf(twc / thc) - atanf(pw / ph);
            const float v   = 0.4052847345693511f * dd * dd;   // 4/pi^2
            const float alpha = v / (1.f - iou + v + EPSF);
            lbox = 1.f - (iou - rho2 / c2 - alpha * v);

            // cls BCE: [log prod(1+e^x) - x_ci] / NC  (4-way ILP product)
            float pr0 = 1.f, pr1 = 1.f, pr2 = 1.f, pr3 = 1.f;
            #pragma unroll
            for (int c = 0; c < NC; c += 4) {
                pr0 *= spf(xv[c]);
                pr1 *= spf(xv[c + 1]);
                pr2 *= spf(xv[c + 2]);
                pr3 *= spf(xv[c + 3]);
            }
            csum = (__logf((pr0 * pr1) * (pr2 * pr3)) - xci) * (1.f / (float)NC);

            // obj correction for first occurrence of this cell (all anchors)
            if (a == 0) {
                bool dup = false;
                #pragma unroll 4
                for (int m = 0; m < n; m++)
                    dup |= (s_key[m] == key);
                corr = dup ? 0.f : -(c0 + c1 + c2v);
            }
        }

        // warps 0-1 hold all contributions; others have zeros and skip atomics
        float rb = warpReduceSum(lbox);
        float rc = warpReduceSum(csum);
        float ro = warpReduceSum(corr);
        if (lid == 0 && t < TPB) {
            atomicAdd(&g_box, rb);
            atomicAdd(&g_cls, rc);
            if (a == 0) atomicAdd(&g_corr[s], ro);
            __threadfence();   // order my REDs before the barrier
        }
        __syncthreads();       // all warps' atomics fenced before finalize
    } else {
        // -------- objectness softplus sweep --------
        // block ranges: [36,111) sc0 (32/thr), [111,130) sc1 (32/thr), [130,140) sc2 (16/thr)
        float gsum = 0.f;
        double* acc;
        if (bid < 111) {
            const int e32 = (bid - 36) * 256 + t;         // cap 19200: exact (75 blocks)
            gsum = sweep32<1600>(p0, e32);
            acc = &g_obj[0];
        } else if (bid < 130) {
            const int e32 = (bid - 111) * 256 + t;        // cap 4800
            if (e32 < 4800) gsum = sweep32<400>(p1, e32);
            acc = &g_obj[1];
        } else {
            const int e16 = (bid - 130) * 256 + t;        // cap 2400
            if (e16 < 2400) gsum = sweep16<100>(p2, e16);
            acc = &g_obj[2];
        }
        float wsum = warpReduceSum(gsum);
        if (lid == 0 && wsum != 0.f) {
            atomicAdd(acc, (double)wsum);
            __threadfence();
        }
        __syncthreads();
    }

    // ---------------- device-side finalize (last block) ----------------
    if (t == 0) {
        __threadfence();
        unsigned old = atomicAdd(&g_done, 1u);
        if (old == gridDim.x - 1) {
            const double cnt[3] = {614400.0, 153600.0, 38400.0};
            double lod = 0.0;
            for (int k = 0; k < 3; k++)
                lod += (g_obj[k] + (double)g_corr[k]) / cnt[k];
            const float lo = (float)lod;
            const float lb = g_box * (1.f / 2304.f);   // N*A*3
            const float lc = g_cls * (1.f / 2304.f);
            const float total = 0.05f * lb + 1.0f * lo + 0.5f * lc;
            float vals[5] = {total, lb, lo, lc, 0.f};
            for (int i = 0; i < out_size; i++)
                out[i] = (i < 5) ? vals[i] : 0.f;
            // reset for next graph replay
            g_box = 0.f;
            g_cls = 0.f;
            for (int k = 0; k < 3; k++) { g_corr[k] = 0.f; g_obj[k] = 0.0; }
            g_done = 0u;
        }
    }
}

extern "C" void kernel_launch(void* const* d_in, const int* in_sizes, int n_in,
                              void* d_out, int out_size) {
    const float* p0 = (const float*)d_in[0];
    const float* p1 = (const float*)d_in[1];
    const float* p2 = (const float*)d_in[2];
    const float* tg = (const float*)d_in[3];
    (void)in_sizes; (void)n_in;

    // 36 target + 75 + 19 + 10 sweep = 140 blocks: one wave, <=1 block/SM
    fused_kernel<<<140, 256>>>(p0, p1, p2, tg, (float*)d_out, out_size);
}

// round 13
// speedup vs baseline: 1.0701x; 1.0052x over previous
#include <cuda_runtime.h>

#define NA   3
#define NC   20
#define NCH  25      // 5 + NC
#define NT   256     // number of targets
#define TPB  64      // targets per target-block (NT/4)
#define EPSF 1e-7f

// Accumulators. Zero-initialized at module load; the finalizing block
// re-zeroes them so every graph replay starts clean.
__device__ double   g_obj[3];
__device__ float    g_corr[3];
__device__ float    g_box;
__device__ float    g_cls;
__device__ unsigned g_done;

__device__ __forceinline__ float sigmoidf(float x) {
    return 1.f / (1.f + __expf(-x));
}
// factor (1 + e^x) via MUFU
__device__ __forceinline__ float spf(float x) {
    return 1.f + __expf(x);
}
// factor (1 + e^x) via FMA-pipe exp2 bit trick (no MUFU).
// |rel err| ~1e-4, minimax (near-zero bias). Safe for x in [-20, 30].
__device__ __forceinline__ float spf_poly(float x) {
    x = fminf(fmaxf(x, -20.f), 30.f);
    const float y = x * 1.44269504088896f;     // log2(e)
    const float r = rintf(y);
    const float f = y - r;
    // 2^f on [-0.5, 0.5], cubic minimax
    float p = fmaf(f, 0.0558263f, 0.2401536f);
    p = fmaf(f, p, 0.6931531f);
    p = fmaf(f, p, 0.9999993f);
    const int e = (int)r;
    const float s = __int_as_float(__float_as_int(p) + (e << 23));
    return 1.f + s;
}

__device__ __forceinline__ float warpReduceSum(float v) {
    #pragma unroll
    for (int o = 16; o > 0; o >>= 1)
        v += __shfl_xor_sync(0xffffffffu, v, o);
    return v;
}

// product of 8 factors: 6 via MUFU exp, 2 via FMA-pipe poly exp (pipe balance)
__device__ __forceinline__ float prod8(float4 a, float4 b) {
    return ((spf(a.x) * spf(a.y)) * (spf(a.z) * spf_poly(a.w)))
         * ((spf(b.x) * spf(b.y)) * (spf(b.z) * spf_poly(b.w)));
}

// 16-element softplus group-sum; requires HW4 % 4 == 0 (no plane straddle)
template<int HW4>
__device__ __forceinline__ float sweep16(const float* __restrict__ p, int e16) {
    const int f4    = e16 * 4;
    const int plane = f4 / HW4;                 // constant divisor -> mul/shift
    const float4* q = (const float4*)p + f4 + (size_t)HW4 * (24 * plane + 4);
    float4 v0 = q[0], v1 = q[1], v2 = q[2], v3 = q[3];   // MLP = 4
    return __logf(prod8(v0, v1)) + __logf(prod8(v2, v3));
}

__global__ void __launch_bounds__(256) fused_kernel(
    const float* __restrict__ p0,
    const float* __restrict__ p1,
    const float* __restrict__ p2,
    const float* __restrict__ tg,
    float* __restrict__ out, int out_size)
{
    const int bid = blockIdx.x;
    const int t   = threadIdx.x;
    const int lid = t & 31;

    if (bid < 36) {
        // ------- target blocks: (scale, anchor, quarter), 64 targets each -------
        __shared__ float s_t[NT * 6];
        __shared__ int   s_key[NT];
        for (int i = t; i < NT * 6; i += 256) s_t[i] = tg[i];
        __syncthreads();

        const int s = bid / 12;                 // scale
        const int a = (bid / 4) % 3;            // anchor
        const int q4 = bid & 3;                 // quarter
        const int H  = (s == 0) ? 80 : (s == 1) ? 40 : 20;
        const int W  = H;
        const int HW = H * W;
        const float* p = (s == 0) ? p0 : (s == 1) ? p1 : p2;
        const float fw = (float)W, fh = (float)H;

        // every thread computes the key for target t (full table for dedup scan)
        {
            const int   kb = (int)s_t[t * 6 + 0];
            const float kx = s_t[t * 6 + 2];
            const float ky = s_t[t * 6 + 3];
            const int kgi = (int)fminf(fmaxf(kx * fw, 0.f), fw - 1.f);
            const int kgj = (int)fminf(fmaxf(ky * fh, 0.f), fh - 1.f);
            s_key[t] = (kb << 14) | (kgj << 7) | kgi;
        }
        __syncthreads();

        float lbox = 0.f, csum = 0.f, corr = 0.f;
        if (t < TPB) {
            const int n = q4 * TPB + t;         // this thread's target
            const int   bi = (int)s_t[n * 6 + 0];
            const int   ci = (int)s_t[n * 6 + 1];
            const float cx = s_t[n * 6 + 2];
            const float cy = s_t[n * 6 + 3];
            const float tw = s_t[n * 6 + 4];
            const float th = s_t[n * 6 + 5];

            const int gi = (int)fminf(fmaxf(cx * fw, 0.f), fw - 1.f);
            const int gj = (int)fminf(fmaxf(cy * fh, 0.f), fh - 1.f);
            const int key = (bi << 14) | (gj << 7) | gi;

            const float* cellp = p + ((size_t)(bi * NA * NCH + a * NCH)) * HW
                                   + (size_t)gj * W + gi;

            // ---- issue ALL scattered loads up front (high MLP) ----
            const float x0 = cellp[0];
            const float x1 = cellp[HW];
            float xv[NC];
            #pragma unroll
            for (int c = 0; c < NC; c++) xv[c] = cellp[(size_t)(5 + c) * HW];
            const float xci = cellp[(size_t)(5 + ci) * HW];
            float c0 = 0.f, c1 = 0.f, c2v = 0.f;
            const float* op = p + ((size_t)(bi * NA * NCH)) * HW + (size_t)gj * W + gi;
            if (a == 0) {
                c0  = op[(size_t)4 * HW];
                c1  = op[(size_t)(NCH + 4) * HW];
                c2v = op[(size_t)(2 * NCH + 4) * HW];
            }

            const float sx = sigmoidf(x0);
            const float sy = sigmoidf(x1);

            const float twh = tw * fw * 0.5f;
            const float thh = th * fh * 0.5f;
            const float gif = (float)gi, gjf = (float)gj;

            const float px1 = (sx + gif - twh) / fw;
            const float py1 = (sy + gjf - thh) / fh;
            const float px2 = (sx + gif + twh) / fw;
            const float py2 = (sy + gjf + thh) / fh;

            const float tx1 = cx - tw * 0.5f;
            const float ty1 = cy - th * 0.5f;
            const float tx2 = cx + tw * 0.5f;
            const float ty2 = cy + th * 0.5f;

            // CIoU loss
            const float ix1 = fmaxf(px1, tx1), iy1 = fmaxf(py1, ty1);
            const float ix2 = fminf(px2, tx2), iy2 = fminf(py2, ty2);
            const float inter  = fmaxf(ix2 - ix1, 0.f) * fmaxf(iy2 - iy1, 0.f);
            const float area_p = (px2 - px1) * (py2 - py1);
            const float area_t = (tx2 - tx1) * (ty2 - ty1);
            const float uni = area_p + area_t - inter + EPSF;
            const float iou = inter / uni;
            const float ex1 = fminf(px1, tx1), ey1 = fminf(py1, ty1);
            const float ex2 = fmaxf(px2, tx2), ey2 = fmaxf(py2, ty2);
            const float c2  = (ex2 - ex1) * (ex2 - ex1) + (ey2 - ey1) * (ey2 - ey1) + EPSF;
            const float dxc = (px1 + px2) * 0.5f - (tx1 + tx2) * 0.5f;
            const float dyc = (py1 + py2) * 0.5f - (ty1 + ty2) * 0.5f;
            const float rho2 = dxc * dxc + dyc * dyc;
            const float pw  = fmaxf(px2 - px1, EPSF);
            const float ph  = fmaxf(py2 - py1, EPSF);
            const float twc = fmaxf(tx2 - tx1, EPSF);
            const float thc = fmaxf(ty2 - ty1, EPSF);
            const float dd  = atanf(twc / thc) - atanf(pw / ph);
            const float v   = 0.4052847345693511f * dd * dd;   // 4/pi^2
            const float alpha = v / (1.f - iou + v + EPSF);
            lbox = 1.f - (iou - rho2 / c2 - alpha * v);

            // cls BCE: [log prod(1+e^x) - x_ci] / NC  (4-way ILP product)
            float pr0 = 1.f, pr1 = 1.f, pr2 = 1.f, pr3 = 1.f;
            #pragma unroll
            for (int c = 0; c < NC; c += 4) {
                pr0 *= spf(xv[c]);
                pr1 *= spf(xv[c + 1]);
                pr2 *= spf(xv[c + 2]);
                pr3 *= spf(xv[c + 3]);
            }
            csum = (__logf((pr0 * pr1) * (pr2 * pr3)) - xci) * (1.f / (float)NC);

            // obj correction for first occurrence of this cell (all anchors)
            if (a == 0) {
                bool dup = false;
                #pragma unroll 4
                for (int m = 0; m < n; m++)
                    dup |= (s_key[m] == key);
                corr = dup ? 0.f : -(c0 + c1 + c2v);
            }
        }

        // warps 0-1 hold all contributions; others have zeros and skip atomics
        float rb = warpReduceSum(lbox);
        float rc = warpReduceSum(csum);
        float ro = warpReduceSum(corr);
        if (lid == 0 && t < TPB) {
            atomicAdd(&g_box, rb);
            atomicAdd(&g_cls, rc);
            if (a == 0) atomicAdd(&g_corr[s], ro);
            __threadfence();   // order my REDs before the barrier
        }
        __syncthreads();       // all warps' atomics fenced before finalize
    } else {
        // -------- objectness softplus sweep: 16 elems (4 float4) / thread --------
        // block ranges: [36,186) sc0, [186,224) sc1, [224,234) sc2
        float gsum = 0.f;
        double* acc;
        if (bid < 186) {
            const int e16 = (bid - 36) * 256 + t;         // cap 38400: exact (150 blocks)
            gsum = sweep16<1600>(p0, e16);
            acc = &g_obj[0];
        } else if (bid < 224) {
            const int e16 = (bid - 186) * 256 + t;        // cap 9600
            if (e16 < 9600) gsum = sweep16<400>(p1, e16);
            acc = &g_obj[1];
        } else {
            const int e16 = (bid - 224) * 256 + t;        // cap 2400
            if (e16 < 2400) gsum = sweep16<100>(p2, e16);
            acc = &g_obj[2];
        }
        float wsum = warpReduceSum(gsum);
        if (lid == 0 && wsum != 0.f) {
            atomicAdd(acc, (double)wsum);
            __threadfence();
        }
        __syncthreads();
    }

    // ---------------- device-side finalize (last block) ----------------
    if (t == 0) {
        __threadfence();
        unsigned old = atomicAdd(&g_done, 1u);
        if (old == gridDim.x - 1) {
            const double cnt[3] = {614400.0, 153600.0, 38400.0};
            double lod = 0.0;
            for (int k = 0; k < 3; k++)
                lod += (g_obj[k] + (double)g_corr[k]) / cnt[k];
            const float lo = (float)lod;
            const float lb = g_box * (1.f / 2304.f);   // N*A*3
            const float lc = g_cls * (1.f / 2304.f);
            const float total = 0.05f * lb + 1.0f * lo + 0.5f * lc;
            float vals[5] = {total, lb, lo, lc, 0.f};
            for (int i = 0; i < out_size; i++)
                out[i] = (i < 5) ? vals[i] : 0.f;
            // reset for next graph replay
            g_box = 0.f;
            g_cls = 0.f;
            for (int k = 0; k < 3; k++) { g_corr[k] = 0.f; g_obj[k] = 0.0; }
            g_done = 0u;
        }
    }
}

extern "C" void kernel_launch(void* const* d_in, const int* in_sizes, int n_in,
                              void* d_out, int out_size) {
    const float* p0 = (const float*)d_in[0];
    const float* p1 = (const float*)d_in[1];
    const float* p2 = (const float*)d_in[2];
    const float* tg = (const float*)d_in[3];
    (void)in_sizes; (void)n_in;

    // 36 target + 150 + 38 + 10 sweep = 234 blocks: ~2 CTAs/SM concurrent
    fused_kernel<<<234, 256>>>(p0, p1, p2, tg, (float*)d_out, out_size);
}